// round 1
// baseline (speedup 1.0000x reference)
#include <cuda_runtime.h>

#define SLEN 2048
#define BSZ  2
#define EMB  1024
#define NH   16
#define DHD  64
#define PFW  16
#define MTOK (SLEN*BSZ)

// ---------------- scratch (static device arrays; no allocation) -------------
__device__ float g_xn[MTOK*EMB];
__device__ float g_q [MTOK*EMB];
__device__ float g_k [MTOK*EMB];
__device__ float g_v [MTOK*EMB];
__device__ float g_att[MTOK*EMB];

// ---------------- LayerNorm: one block per token row -----------------------
__global__ void __launch_bounds__(256) ln_kernel(
    const float* __restrict__ x,
    const float* __restrict__ gamma,
    const float* __restrict__ beta,
    float* __restrict__ out)
{
    int row = blockIdx.x;
    int tid = threadIdx.x;
    const float4 xv = ((const float4*)(x + (size_t)row * EMB))[tid];
    float s  = xv.x + xv.y + xv.z + xv.w;
    float s2 = xv.x*xv.x + xv.y*xv.y + xv.z*xv.z + xv.w*xv.w;
    #pragma unroll
    for (int o = 16; o > 0; o >>= 1) {
        s  += __shfl_xor_sync(0xffffffffu, s,  o);
        s2 += __shfl_xor_sync(0xffffffffu, s2, o);
    }
    __shared__ float rs[8], rs2[8];
    __shared__ float mean_s, rstd_s;
    int w = tid >> 5, l = tid & 31;
    if (l == 0) { rs[w] = s; rs2[w] = s2; }
    __syncthreads();
    if (tid == 0) {
        float ts = 0.f, ts2 = 0.f;
        #pragma unroll
        for (int i = 0; i < 8; i++) { ts += rs[i]; ts2 += rs2[i]; }
        float mean = ts * (1.0f / EMB);
        float var  = ts2 * (1.0f / EMB) - mean * mean;
        mean_s = mean;
        rstd_s = rsqrtf(var + 1e-5f);
    }
    __syncthreads();
    float mean = mean_s, r = rstd_s;
    float4 gv = ((const float4*)gamma)[tid];
    float4 bv = ((const float4*)beta)[tid];
    float4 o;
    o.x = (xv.x - mean) * r * gv.x + bv.x;
    o.y = (xv.y - mean) * r * gv.y + bv.y;
    o.z = (xv.z - mean) * r * gv.z + bv.z;
    o.w = (xv.w - mean) * r * gv.w + bv.w;
    ((float4*)(out + (size_t)row * EMB))[tid] = o;
}

// ---------------- fp32 tiled SGEMM: C = A[M,K] @ B[K,N] + bias (+res) ------
#define BM 128
#define BN 128
#define BK 8
#define TM 8
#define TN 8

template<bool ADD_RES>
__global__ void __launch_bounds__(256) sgemm_kernel(
    const float* __restrict__ A,
    const float* __restrict__ B,
    const float* __restrict__ bias,
    const float* __restrict__ res,
    float* __restrict__ C,
    int M, int N, int K)
{
    __shared__ float As[BK][BM];
    __shared__ float Bs[BK][BN];

    int tid = threadIdx.x;
    int tx = tid & 15;
    int ty = tid >> 4;
    int bm = blockIdx.y * BM;
    int bn = blockIdx.x * BN;

    int a_row = tid >> 1;
    int a_col = (tid & 1) * 4;
    int b_row = tid >> 5;
    int b_col = (tid & 31) * 4;

    const float* Aptr = A + (size_t)(bm + a_row) * K + a_col;
    const float* Bptr = B + (size_t)b_row * N + bn + b_col;

    float acc[TM][TN];
    #pragma unroll
    for (int i = 0; i < TM; i++)
        #pragma unroll
        for (int j = 0; j < TN; j++) acc[i][j] = 0.f;

    for (int k0 = 0; k0 < K; k0 += BK) {
        float4 av = *(const float4*)(Aptr + k0);
        float4 bvv = *(const float4*)(Bptr + (size_t)k0 * N);
        As[a_col + 0][a_row] = av.x;
        As[a_col + 1][a_row] = av.y;
        As[a_col + 2][a_row] = av.z;
        As[a_col + 3][a_row] = av.w;
        *(float4*)(&Bs[b_row][b_col]) = bvv;
        __syncthreads();
        #pragma unroll
        for (int kk = 0; kk < BK; kk++) {
            float a_reg[TM], b_reg[TN];
            #pragma unroll
            for (int i = 0; i < TM; i++) a_reg[i] = As[kk][ty * TM + i];
            #pragma unroll
            for (int j = 0; j < TN; j++) b_reg[j] = Bs[kk][tx * TN + j];
            #pragma unroll
            for (int i = 0; i < TM; i++)
                #pragma unroll
                for (int j = 0; j < TN; j++)
                    acc[i][j] += a_reg[i] * b_reg[j];
        }
        __syncthreads();
    }

    int colbase = bn + tx * TN;
    #pragma unroll
    for (int i = 0; i < TM; i++) {
        int row = bm + ty * TM + i;
        float* crow = C + (size_t)row * N + colbase;
        const float* rrow = ADD_RES ? (res + (size_t)row * N + colbase) : nullptr;
        #pragma unroll
        for (int j4 = 0; j4 < TN; j4 += 4) {
            float4 v;
            v.x = acc[i][j4 + 0] + bias[colbase + j4 + 0];
            v.y = acc[i][j4 + 1] + bias[colbase + j4 + 1];
            v.z = acc[i][j4 + 2] + bias[colbase + j4 + 2];
            v.w = acc[i][j4 + 3] + bias[colbase + j4 + 3];
            if (ADD_RES) {
                float4 rv = *(const float4*)(rrow + j4);
                v.x += rv.x; v.y += rv.y; v.z += rv.z; v.w += rv.w;
            }
            *(float4*)(crow + j4) = v;
        }
    }
}

// ---------------- sliding-window attention: one warp per head --------------
// scores[s,b,h,p] = q[s,b,h] . K[(s-15+p) mod SL, b, h] / 8 ; softmax over p;
// out = sum_p attn_p * V[(s-15+p) mod SL, b, h]
__global__ void __launch_bounds__(512) attn_kernel(
    const float* __restrict__ Q,
    const float* __restrict__ K,
    const float* __restrict__ V,
    float* __restrict__ O)
{
    int s = blockIdx.x;
    int b = blockIdx.y;
    int h = threadIdx.x >> 5;
    int lane = threadIdx.x & 31;
    int t = s * BSZ + b;

    const float* qp = Q + (size_t)t * EMB + h * DHD;
    float q0 = qp[lane];
    float q1 = qp[lane + 32];

    float sc[PFW];
    #pragma unroll
    for (int p = 0; p < PFW; p++) {
        int sp = s + p - (PFW - 1);
        if (sp < 0) sp += SLEN;
        const float* kp = K + (size_t)(sp * BSZ + b) * EMB + h * DHD;
        float d = q0 * kp[lane] + q1 * kp[lane + 32];
        #pragma unroll
        for (int o = 16; o > 0; o >>= 1) d += __shfl_xor_sync(0xffffffffu, d, o);
        sc[p] = d * 0.125f;   // 1/sqrt(64)
    }

    float mx = sc[0];
    #pragma unroll
    for (int p = 1; p < PFW; p++) mx = fmaxf(mx, sc[p]);
    float sum = 0.f;
    #pragma unroll
    for (int p = 0; p < PFW; p++) { sc[p] = __expf(sc[p] - mx); sum += sc[p]; }
    float inv = 1.0f / sum;

    float o0 = 0.f, o1 = 0.f;
    #pragma unroll
    for (int p = 0; p < PFW; p++) {
        int sp = s + p - (PFW - 1);
        if (sp < 0) sp += SLEN;
        const float* vp = V + (size_t)(sp * BSZ + b) * EMB + h * DHD;
        float w = sc[p] * inv;
        o0 += w * vp[lane];
        o1 += w * vp[lane + 32];
    }
    float* op = O + (size_t)t * EMB + h * DHD;
    op[lane] = o0;
    op[lane + 32] = o1;
}

// ---------------- launch ----------------------------------------------------
extern "C" void kernel_launch(void* const* d_in, const int* in_sizes, int n_in,
                              void* d_out, int out_size)
{
    const float* x    = (const float*)d_in[0];
    const float* ln_g = (const float*)d_in[1];
    const float* ln_b = (const float*)d_in[2];
    const float* Wq   = (const float*)d_in[3];
    const float* bq   = (const float*)d_in[4];
    const float* Wk   = (const float*)d_in[5];
    const float* bk   = (const float*)d_in[6];
    const float* Wv   = (const float*)d_in[7];
    const float* bv   = (const float*)d_in[8];
    const float* Wo   = (const float*)d_in[9];
    const float* bo   = (const float*)d_in[10];
    float* out = (float*)d_out;

    float *xn, *q, *k, *v, *att;
    cudaGetSymbolAddress((void**)&xn,  g_xn);
    cudaGetSymbolAddress((void**)&q,   g_q);
    cudaGetSymbolAddress((void**)&k,   g_k);
    cudaGetSymbolAddress((void**)&v,   g_v);
    cudaGetSymbolAddress((void**)&att, g_att);

    ln_kernel<<<MTOK, 256>>>(x, ln_g, ln_b, xn);

    dim3 gg(EMB / BN, MTOK / BM);
    sgemm_kernel<false><<<gg, 256>>>(xn, Wq, bq, nullptr, q, MTOK, EMB, EMB);
    sgemm_kernel<false><<<gg, 256>>>(xn, Wk, bk, nullptr, k, MTOK, EMB, EMB);
    sgemm_kernel<false><<<gg, 256>>>(xn, Wv, bv, nullptr, v, MTOK, EMB, EMB);

    attn_kernel<<<dim3(SLEN, BSZ), 512>>>(q, k, v, att);

    sgemm_kernel<true><<<gg, 256>>>(att, Wo, bo, x, out, MTOK, EMB, EMB);
}

// round 3
// speedup vs baseline: 1.9832x; 1.9832x over previous
#include <cuda_runtime.h>
#include <cuda_bf16.h>
#include <cstdint>

#define SLEN 2048
#define BSZ  2
#define EMB  1024
#define NH   16
#define DHD  64
#define PFW  16
#define MTOK (SLEN*BSZ)
#define KTOT 3072          // 3 * EMB (bf16x3 split)
#define GBK  32            // K per mainloop chunk (bf16 elems)
#define NCHUNK (KTOT/GBK)  // 96
#define GBM  128
#define GBN  256
#define STAGES 4
#define ROWB 80            // padded smem row bytes (64 data + 16 pad)
#define ASTG (GBM*ROWB)    // 10240
#define BSTG (GBN*ROWB)    // 20480
#define STGB (ASTG+BSTG)   // 30720
#define GEMM_SMEM (STAGES*STGB)  // 122880

// ---------------- scratch (static device arrays; no allocation) -------------
__device__ __align__(16) __nv_bfloat16 g_xn2 [MTOK*KTOT];
__device__ __align__(16) __nv_bfloat16 g_att2[MTOK*KTOT];
__device__ __align__(16) __nv_bfloat16 g_w2  [4*EMB*KTOT];
__device__ float g_q[MTOK*EMB];
__device__ float g_k[MTOK*EMB];
__device__ float g_v[MTOK*EMB];

// ---------------- PTX helpers ------------------------------------------------
__device__ __forceinline__ uint32_t s2u(const void* p) {
    uint32_t a;
    asm("{ .reg .u64 t; cvta.to.shared.u64 t, %1; cvt.u32.u64 %0, t; }" : "=r"(a) : "l"(p));
    return a;
}
__device__ __forceinline__ void cp16(uint32_t dst, const void* src) {
    asm volatile("cp.async.cg.shared.global [%0], [%1], 16;" :: "r"(dst), "l"(src));
}
#define CP_COMMIT() asm volatile("cp.async.commit_group;" ::: "memory")

__device__ __forceinline__ void ldsm4(uint32_t* r, uint32_t addr) {
    asm volatile("ldmatrix.sync.aligned.m8n8.x4.shared.b16 {%0,%1,%2,%3}, [%4];"
        : "=r"(r[0]), "=r"(r[1]), "=r"(r[2]), "=r"(r[3]) : "r"(addr));
}
__device__ __forceinline__ void mma16816(float* d, const uint32_t* a,
                                         uint32_t b0, uint32_t b1) {
    asm volatile("mma.sync.aligned.m16n8k16.row.col.f32.bf16.bf16.f32 "
        "{%0,%1,%2,%3}, {%4,%5,%6,%7}, {%8,%9}, {%0,%1,%2,%3};"
        : "+f"(d[0]), "+f"(d[1]), "+f"(d[2]), "+f"(d[3])
        : "r"(a[0]), "r"(a[1]), "r"(a[2]), "r"(a[3]), "r"(b0), "r"(b1));
}

// ---------------- weight prep: W[K,N] fp32 -> B2[N,3K] bf16 (hi,hi,lo) ------
__global__ void __launch_bounds__(256) wprep_kernel(
    const float* __restrict__ W0, const float* __restrict__ W1,
    const float* __restrict__ W2, const float* __restrict__ W3,
    __nv_bfloat16* __restrict__ B2all)
{
    const float* W = (blockIdx.z == 0) ? W0 : (blockIdx.z == 1) ? W1
                   : (blockIdx.z == 2) ? W2 : W3;
    __nv_bfloat16* B2 = B2all + (size_t)blockIdx.z * EMB * KTOT;
    __shared__ float tile[32][33];
    int n0 = blockIdx.x * 32;
    int k0 = blockIdx.y * 32;
    int tx = threadIdx.x & 31;
    int ty = threadIdx.x >> 5;
    #pragma unroll
    for (int r = ty; r < 32; r += 8)
        tile[r][tx] = W[(size_t)(k0 + r) * EMB + n0 + tx];   // tile[k][n]
    __syncthreads();
    #pragma unroll
    for (int r = ty; r < 32; r += 8) {
        float x = tile[tx][r];                                // W[k0+tx][n0+r]
        __nv_bfloat16 hi = __float2bfloat16(x);
        __nv_bfloat16 lo = __float2bfloat16(x - __bfloat162float(hi));
        size_t base = (size_t)(n0 + r) * KTOT + (k0 + tx);
        B2[base]          = hi;
        B2[base + EMB]    = hi;
        B2[base + 2*EMB]  = lo;
    }
}

// ---------------- LayerNorm -> split bf16 A' = (hi, lo, hi) ----------------
__global__ void __launch_bounds__(256) ln_kernel(
    const float* __restrict__ x,
    const float* __restrict__ gamma,
    const float* __restrict__ beta,
    __nv_bfloat16* __restrict__ xn2)
{
    int row = blockIdx.x;
    int tid = threadIdx.x;
    const float4 xv = ((const float4*)(x + (size_t)row * EMB))[tid];
    float s  = xv.x + xv.y + xv.z + xv.w;
    float s2 = xv.x*xv.x + xv.y*xv.y + xv.z*xv.z + xv.w*xv.w;
    #pragma unroll
    for (int o = 16; o > 0; o >>= 1) {
        s  += __shfl_xor_sync(0xffffffffu, s,  o);
        s2 += __shfl_xor_sync(0xffffffffu, s2, o);
    }
    __shared__ float rs[8], rs2[8];
    __shared__ float mean_s, rstd_s;
    int w = tid >> 5, l = tid & 31;
    if (l == 0) { rs[w] = s; rs2[w] = s2; }
    __syncthreads();
    if (tid == 0) {
        float ts = 0.f, ts2 = 0.f;
        #pragma unroll
        for (int i = 0; i < 8; i++) { ts += rs[i]; ts2 += rs2[i]; }
        float mean = ts * (1.0f / EMB);
        float var  = ts2 * (1.0f / EMB) - mean * mean;
        mean_s = mean;
        rstd_s = rsqrtf(var + 1e-5f);
    }
    __syncthreads();
    float mean = mean_s, r = rstd_s;
    float4 gv = ((const float4*)gamma)[tid];
    float4 bv = ((const float4*)beta)[tid];
    float o[4];
    o[0] = (xv.x - mean) * r * gv.x + bv.x;
    o[1] = (xv.y - mean) * r * gv.y + bv.y;
    o[2] = (xv.z - mean) * r * gv.z + bv.z;
    o[3] = (xv.w - mean) * r * gv.w + bv.w;
    __nv_bfloat16 hi[4], lo[4];
    #pragma unroll
    for (int i = 0; i < 4; i++) {
        hi[i] = __float2bfloat16(o[i]);
        lo[i] = __float2bfloat16(o[i] - __bfloat162float(hi[i]));
    }
    __nv_bfloat16* base = xn2 + (size_t)row * KTOT + tid * 4;
    *(uint2*)(base)           = *(uint2*)hi;   // seg0 hi
    *(uint2*)(base + EMB)     = *(uint2*)lo;   // seg1 lo
    *(uint2*)(base + 2*EMB)   = *(uint2*)hi;   // seg2 hi
}

// ---------------- HMMA bf16 GEMM: C = A2 @ B2^T + bias (+res) --------------
// A2: [M, KTOT] bf16 row-major.  B2: [N, KTOT] bf16 row-major.
// CTA tile 128x256, warp tile 64x64, BK=32, 4-stage cp.async pipeline.
__device__ __forceinline__ void load_stage(
    const __nv_bfloat16* __restrict__ A2, const __nv_bfloat16* __restrict__ B2,
    int bm, int bn, int c, uint32_t sA, uint32_t sB, int tid)
{
    #pragma unroll
    for (int j = 0; j < 2; j++) {
        int i = tid + 256 * j;
        int row = i >> 2, ch = i & 3;
        cp16(sA + row * ROWB + ch * 16,
             A2 + (size_t)(bm + row) * KTOT + c * GBK + ch * 8);
    }
    #pragma unroll
    for (int j = 0; j < 4; j++) {
        int i = tid + 256 * j;
        int row = i >> 2, ch = i & 3;
        cp16(sB + row * ROWB + ch * 16,
             B2 + (size_t)(bn + row) * KTOT + c * GBK + ch * 8);
    }
}

__global__ void __launch_bounds__(256, 1) gemm_mma(
    const __nv_bfloat16* __restrict__ A2,
    const __nv_bfloat16* __restrict__ B2,
    const float* __restrict__ bias,
    const float* __restrict__ res,
    float* __restrict__ C,
    int add_res)
{
    extern __shared__ char smem[];
    uint32_t sb = s2u(smem);
    int tid = threadIdx.x;
    int w = tid >> 5, l = tid & 31;
    int bm = blockIdx.y * GBM;
    int bn = blockIdx.x * GBN;
    int wm = (w & 1) * 64;     // warp M offset within CTA
    int wn = (w >> 1) * 64;    // warp N offset within CTA

    float acc[4][8][4];
    #pragma unroll
    for (int i = 0; i < 4; i++)
        #pragma unroll
        for (int j = 0; j < 8; j++)
            #pragma unroll
            for (int t = 0; t < 4; t++) acc[i][j][t] = 0.f;

    // prologue: fill STAGES-1 stages
    #pragma unroll
    for (int c = 0; c < STAGES - 1; c++) {
        load_stage(A2, B2, bm, bn, c, sb + c * STGB, sb + c * STGB + ASTG, tid);
        CP_COMMIT();
    }

    // per-lane ldmatrix addressing
    uint32_t arowoff = (uint32_t)(wm + (l & 15)) * ROWB + ((l >> 4) << 4);
    uint32_t browoff = (uint32_t)(wn + (l & 15)) * ROWB + ((l >> 4) << 4);

    for (int c = 0; c < NCHUNK; c++) {
        asm volatile("cp.async.wait_group %0;" :: "n"(STAGES - 2) : "memory");
        __syncthreads();
        int s = c & (STAGES - 1);
        uint32_t sA = sb + s * STGB;
        uint32_t sB = sA + ASTG;

        #pragma unroll
        for (int ks = 0; ks < 2; ks++) {
            uint32_t af[4][4], br[4][4];
            #pragma unroll
            for (int mt = 0; mt < 4; mt++)
                ldsm4(af[mt], sA + arowoff + mt * (16 * ROWB) + ks * 32);
            #pragma unroll
            for (int bt = 0; bt < 4; bt++)
                ldsm4(br[bt], sB + browoff + bt * (16 * ROWB) + ks * 32);
            #pragma unroll
            for (int mt = 0; mt < 4; mt++)
                #pragma unroll
                for (int bt = 0; bt < 4; bt++) {
                    mma16816(acc[mt][2 * bt],     af[mt], br[bt][0], br[bt][2]);
                    mma16816(acc[mt][2 * bt + 1], af[mt], br[bt][1], br[bt][3]);
                }
        }

        int cn = c + STAGES - 1;
        if (cn < NCHUNK) {
            int sn = cn & (STAGES - 1);
            load_stage(A2, B2, bm, bn, cn, sb + sn * STGB, sb + sn * STGB + ASTG, tid);
        }
        CP_COMMIT();
    }

    // epilogue: acc[mt][nt][4] -> C
    int rbase = bm + wm + (l >> 2);
    int cbase = bn + wn + 2 * (l & 3);
    #pragma unroll
    for (int mt = 0; mt < 4; mt++) {
        #pragma unroll
        for (int nt = 0; nt < 8; nt++) {
            int col = cbase + nt * 8;
            float bx = bias[col], by = bias[col + 1];
            int r0 = rbase + mt * 16;
            int r1 = r0 + 8;
            float2 v0, v1;
            v0.x = acc[mt][nt][0] + bx;
            v0.y = acc[mt][nt][1] + by;
            v1.x = acc[mt][nt][2] + bx;
            v1.y = acc[mt][nt][3] + by;
            if (add_res) {
                float2 q0 = *(const float2*)(res + (size_t)r0 * EMB + col);
                float2 q1 = *(const float2*)(res + (size_t)r1 * EMB + col);
                v0.x += q0.x; v0.y += q0.y;
                v1.x += q1.x; v1.y += q1.y;
            }
            *(float2*)(C + (size_t)r0 * EMB + col) = v0;
            *(float2*)(C + (size_t)r1 * EMB + col) = v1;
        }
    }
}

// ---------------- sliding-window attention -> split bf16 output ------------
__global__ void __launch_bounds__(512) attn_kernel(
    const float* __restrict__ Q,
    const float* __restrict__ K,
    const float* __restrict__ V,
    __nv_bfloat16* __restrict__ O2)
{
    int s = blockIdx.x;
    int b = blockIdx.y;
    int h = threadIdx.x >> 5;
    int lane = threadIdx.x & 31;
    int t = s * BSZ + b;

    const float* qp = Q + (size_t)t * EMB + h * DHD;
    float q0 = qp[lane];
    float q1 = qp[lane + 32];

    float sc[PFW];
    #pragma unroll
    for (int p = 0; p < PFW; p++) {
        int sp = s + p - (PFW - 1);
        if (sp < 0) sp += SLEN;
        const float* kp = K + (size_t)(sp * BSZ + b) * EMB + h * DHD;
        float d = q0 * kp[lane] + q1 * kp[lane + 32];
        #pragma unroll
        for (int o = 16; o > 0; o >>= 1) d += __shfl_xor_sync(0xffffffffu, d, o);
        sc[p] = d * 0.125f;
    }

    float mx = sc[0];
    #pragma unroll
    for (int p = 1; p < PFW; p++) mx = fmaxf(mx, sc[p]);
    float sum = 0.f;
    #pragma unroll
    for (int p = 0; p < PFW; p++) { sc[p] = __expf(sc[p] - mx); sum += sc[p]; }
    float inv = 1.0f / sum;

    float o0 = 0.f, o1 = 0.f;
    #pragma unroll
    for (int p = 0; p < PFW; p++) {
        int sp = s + p - (PFW - 1);
        if (sp < 0) sp += SLEN;
        const float* vp = V + (size_t)(sp * BSZ + b) * EMB + h * DHD;
        float wgt = sc[p] * inv;
        o0 += wgt * vp[lane];
        o1 += wgt * vp[lane + 32];
    }
    __nv_bfloat16 h0 = __float2bfloat16(o0);
    __nv_bfloat16 l0 = __float2bfloat16(o0 - __bfloat162float(h0));
    __nv_bfloat16 h1 = __float2bfloat16(o1);
    __nv_bfloat16 l1 = __float2bfloat16(o1 - __bfloat162float(h1));
    __nv_bfloat16* op = O2 + (size_t)t * KTOT + h * DHD;
    op[lane]            = h0;  op[lane + 32]            = h1;   // seg0 hi
    op[EMB + lane]      = l0;  op[EMB + lane + 32]      = l1;   // seg1 lo
    op[2*EMB + lane]    = h0;  op[2*EMB + lane + 32]    = h1;   // seg2 hi
}

// ---------------- launch ----------------------------------------------------
extern "C" void kernel_launch(void* const* d_in, const int* in_sizes, int n_in,
                              void* d_out, int out_size)
{
    const float* x    = (const float*)d_in[0];
    const float* ln_g = (const float*)d_in[1];
    const float* ln_b = (const float*)d_in[2];
    const float* Wq   = (const float*)d_in[3];
    const float* bq   = (const float*)d_in[4];
    const float* Wk   = (const float*)d_in[5];
    const float* bk   = (const float*)d_in[6];
    const float* Wv   = (const float*)d_in[7];
    const float* bv   = (const float*)d_in[8];
    const float* Wo   = (const float*)d_in[9];
    const float* bo   = (const float*)d_in[10];
    float* out = (float*)d_out;

    __nv_bfloat16 *xn2, *att2, *w2;
    float *q, *k, *v;
    cudaGetSymbolAddress((void**)&xn2,  g_xn2);
    cudaGetSymbolAddress((void**)&att2, g_att2);
    cudaGetSymbolAddress((void**)&w2,   g_w2);
    cudaGetSymbolAddress((void**)&q,    g_q);
    cudaGetSymbolAddress((void**)&k,    g_k);
    cudaGetSymbolAddress((void**)&v,    g_v);

    cudaFuncSetAttribute(gemm_mma, cudaFuncAttributeMaxDynamicSharedMemorySize, GEMM_SMEM);

    wprep_kernel<<<dim3(32, 32, 4), 256>>>(Wq, Wk, Wv, Wo, w2);
    ln_kernel<<<MTOK, 256>>>(x, ln_g, ln_b, xn2);

    dim3 gg(EMB / GBN, MTOK / GBM);   // (4, 32)
    const size_t WSTRIDE = (size_t)EMB * KTOT;
    gemm_mma<<<gg, 256, GEMM_SMEM>>>(xn2, w2 + 0*WSTRIDE, bq, x, q, 0);
    gemm_mma<<<gg, 256, GEMM_SMEM>>>(xn2, w2 + 1*WSTRIDE, bk, x, k, 0);
    gemm_mma<<<gg, 256, GEMM_SMEM>>>(xn2, w2 + 2*WSTRIDE, bv, x, v, 0);

    attn_kernel<<<dim3(SLEN, BSZ), 512>>>(q, k, v, att2);

    gemm_mma<<<gg, 256, GEMM_SMEM>>>(att2, w2 + 3*WSTRIDE, bo, x, out, 1);
}

// round 4
// speedup vs baseline: 2.0812x; 1.0494x over previous
#include <cuda_runtime.h>
#include <cuda_bf16.h>
#include <cstdint>

#define SLEN 2048
#define BSZ  2
#define EMB  1024
#define NH   16
#define DHD  64
#define PFW  16
#define MTOK (SLEN*BSZ)
#define KTOT 3072          // 3 * EMB (bf16x3 split)
#define GBK  32            // K per mainloop chunk (bf16 elems)
#define NCHUNK (KTOT/GBK)  // 96
#define GBM  128
#define GBN  256
#define STAGES 4
#define ROWB 80            // padded smem row bytes (64 data + 16 pad)
#define ASTG (GBM*ROWB)    // 10240
#define BSTG (GBN*ROWB)    // 20480
#define STGB (ASTG+BSTG)   // 30720
#define GEMM_SMEM (STAGES*STGB)  // 122880
#define GTHR 512

// ---------------- scratch (static device arrays; no allocation) -------------
__device__ __align__(16) __nv_bfloat16 g_xn2 [MTOK*KTOT];
__device__ __align__(16) __nv_bfloat16 g_att2[MTOK*KTOT];
__device__ __align__(16) __nv_bfloat16 g_w2  [4*EMB*KTOT];
__device__ float g_q[MTOK*EMB];
__device__ float g_k[MTOK*EMB];
__device__ float g_v[MTOK*EMB];

// ---------------- PTX helpers ------------------------------------------------
__device__ __forceinline__ uint32_t s2u(const void* p) {
    uint32_t a;
    asm("{ .reg .u64 t; cvta.to.shared.u64 t, %1; cvt.u32.u64 %0, t; }" : "=r"(a) : "l"(p));
    return a;
}
__device__ __forceinline__ void cp16(uint32_t dst, const void* src) {
    asm volatile("cp.async.cg.shared.global [%0], [%1], 16;" :: "r"(dst), "l"(src));
}
#define CP_COMMIT() asm volatile("cp.async.commit_group;" ::: "memory")

__device__ __forceinline__ void ldsm4(uint32_t* r, uint32_t addr) {
    asm volatile("ldmatrix.sync.aligned.m8n8.x4.shared.b16 {%0,%1,%2,%3}, [%4];"
        : "=r"(r[0]), "=r"(r[1]), "=r"(r[2]), "=r"(r[3]) : "r"(addr));
}
__device__ __forceinline__ void mma16816(float* d, const uint32_t* a,
                                         uint32_t b0, uint32_t b1) {
    asm volatile("mma.sync.aligned.m16n8k16.row.col.f32.bf16.bf16.f32 "
        "{%0,%1,%2,%3}, {%4,%5,%6,%7}, {%8,%9}, {%0,%1,%2,%3};"
        : "+f"(d[0]), "+f"(d[1]), "+f"(d[2]), "+f"(d[3])
        : "r"(a[0]), "r"(a[1]), "r"(a[2]), "r"(a[3]), "r"(b0), "r"(b1));
}

// ---------------- weight prep: W[K,N] fp32 -> B2[N,3K] bf16 (hi,hi,lo) ------
__global__ void __launch_bounds__(256) wprep_kernel(
    const float* __restrict__ W0, const float* __restrict__ W1,
    const float* __restrict__ W2, const float* __restrict__ W3,
    __nv_bfloat16* __restrict__ B2all)
{
    const float* W = (blockIdx.z == 0) ? W0 : (blockIdx.z == 1) ? W1
                   : (blockIdx.z == 2) ? W2 : W3;
    __nv_bfloat16* B2 = B2all + (size_t)blockIdx.z * EMB * KTOT;
    __shared__ float tile[32][33];
    int n0 = blockIdx.x * 32;
    int k0 = blockIdx.y * 32;
    int tx = threadIdx.x & 31;
    int ty = threadIdx.x >> 5;
    #pragma unroll
    for (int r = ty; r < 32; r += 8)
        tile[r][tx] = W[(size_t)(k0 + r) * EMB + n0 + tx];   // tile[k][n]
    __syncthreads();
    #pragma unroll
    for (int r = ty; r < 32; r += 8) {
        float x = tile[tx][r];                                // W[k0+tx][n0+r]
        __nv_bfloat16 hi = __float2bfloat16(x);
        __nv_bfloat16 lo = __float2bfloat16(x - __bfloat162float(hi));
        size_t base = (size_t)(n0 + r) * KTOT + (k0 + tx);
        B2[base]          = hi;
        B2[base + EMB]    = hi;
        B2[base + 2*EMB]  = lo;
    }
}

// ---------------- LayerNorm -> split bf16 A' = (hi, lo, hi) ----------------
__global__ void __launch_bounds__(256) ln_kernel(
    const float* __restrict__ x,
    const float* __restrict__ gamma,
    const float* __restrict__ beta,
    __nv_bfloat16* __restrict__ xn2)
{
    int row = blockIdx.x;
    int tid = threadIdx.x;
    const float4 xv = ((const float4*)(x + (size_t)row * EMB))[tid];
    float s  = xv.x + xv.y + xv.z + xv.w;
    float s2 = xv.x*xv.x + xv.y*xv.y + xv.z*xv.z + xv.w*xv.w;
    #pragma unroll
    for (int o = 16; o > 0; o >>= 1) {
        s  += __shfl_xor_sync(0xffffffffu, s,  o);
        s2 += __shfl_xor_sync(0xffffffffu, s2, o);
    }
    __shared__ float rs[8], rs2[8];
    __shared__ float mean_s, rstd_s;
    int w = tid >> 5, l = tid & 31;
    if (l == 0) { rs[w] = s; rs2[w] = s2; }
    __syncthreads();
    if (tid == 0) {
        float ts = 0.f, ts2 = 0.f;
        #pragma unroll
        for (int i = 0; i < 8; i++) { ts += rs[i]; ts2 += rs2[i]; }
        float mean = ts * (1.0f / EMB);
        float var  = ts2 * (1.0f / EMB) - mean * mean;
        mean_s = mean;
        rstd_s = rsqrtf(var + 1e-5f);
    }
    __syncthreads();
    float mean = mean_s, r = rstd_s;
    float4 gv = ((const float4*)gamma)[tid];
    float4 bv = ((const float4*)beta)[tid];
    float o[4];
    o[0] = (xv.x - mean) * r * gv.x + bv.x;
    o[1] = (xv.y - mean) * r * gv.y + bv.y;
    o[2] = (xv.z - mean) * r * gv.z + bv.z;
    o[3] = (xv.w - mean) * r * gv.w + bv.w;
    __nv_bfloat16 hi[4], lo[4];
    #pragma unroll
    for (int i = 0; i < 4; i++) {
        hi[i] = __float2bfloat16(o[i]);
        lo[i] = __float2bfloat16(o[i] - __bfloat162float(hi[i]));
    }
    __nv_bfloat16* base = xn2 + (size_t)row * KTOT + tid * 4;
    *(uint2*)(base)           = *(uint2*)hi;   // seg0 hi
    *(uint2*)(base + EMB)     = *(uint2*)lo;   // seg1 lo
    *(uint2*)(base + 2*EMB)   = *(uint2*)hi;   // seg2 hi
}

// ---------------- HMMA bf16 GEMM: C = A2 @ B2^T + bias (+res) --------------
// A2: [M, KTOT] bf16 row-major.  B2: [N, KTOT] bf16 row-major.
// CTA tile 128x256, 16 warps, warp tile 32x64, BK=32, 4-stage cp.async.
__device__ __forceinline__ void load_stage(
    const __nv_bfloat16* __restrict__ A2, const __nv_bfloat16* __restrict__ B2,
    int bm, int bn, int c, uint32_t sA, uint32_t sB, int tid)
{
    {
        int row = tid >> 2, ch = tid & 3;
        cp16(sA + row * ROWB + ch * 16,
             A2 + (size_t)(bm + row) * KTOT + c * GBK + ch * 8);
    }
    #pragma unroll
    for (int j = 0; j < 2; j++) {
        int i = tid + GTHR * j;
        int row = i >> 2, ch = i & 3;
        cp16(sB + row * ROWB + ch * 16,
             B2 + (size_t)(bn + row) * KTOT + c * GBK + ch * 8);
    }
}

__global__ void __launch_bounds__(GTHR, 1) gemm_mma(
    const __nv_bfloat16* __restrict__ A2,
    const __nv_bfloat16* __restrict__ B2,
    const float* __restrict__ bias,
    const float* __restrict__ res,
    float* __restrict__ C,
    int add_res)
{
    extern __shared__ char smem[];
    uint32_t sb = s2u(smem);
    int tid = threadIdx.x;
    int w = tid >> 5, l = tid & 31;
    int bm = blockIdx.y * GBM;
    int bn = blockIdx.x * GBN;
    int wm = (w & 3) * 32;     // warp M offset within CTA (4 positions)
    int wn = (w >> 2) * 64;    // warp N offset within CTA (4 positions)

    float acc[2][8][4];
    #pragma unroll
    for (int i = 0; i < 2; i++)
        #pragma unroll
        for (int j = 0; j < 8; j++)
            #pragma unroll
            for (int t = 0; t < 4; t++) acc[i][j][t] = 0.f;

    // prologue: fill STAGES-1 stages
    #pragma unroll
    for (int c = 0; c < STAGES - 1; c++) {
        load_stage(A2, B2, bm, bn, c, sb + c * STGB, sb + c * STGB + ASTG, tid);
        CP_COMMIT();
    }

    // per-lane ldmatrix addressing (validated fragment mapping from R3)
    uint32_t arowoff = (uint32_t)(wm + (l & 15)) * ROWB + ((l >> 4) << 4);
    uint32_t browoff = (uint32_t)(wn + (l & 15)) * ROWB + ((l >> 4) << 4);

    for (int c = 0; c < NCHUNK; c++) {
        asm volatile("cp.async.wait_group %0;" :: "n"(STAGES - 2) : "memory");
        __syncthreads();
        int s = c & (STAGES - 1);
        uint32_t sA = sb + s * STGB;
        uint32_t sB = sA + ASTG;

        // issue next-stage loads first so LSU overlaps the MMAs below
        int cn = c + STAGES - 1;
        if (cn < NCHUNK) {
            int sn = cn & (STAGES - 1);
            load_stage(A2, B2, bm, bn, cn, sb + sn * STGB, sb + sn * STGB + ASTG, tid);
        }
        CP_COMMIT();

        #pragma unroll
        for (int ks = 0; ks < 2; ks++) {
            uint32_t af[2][4], br[4][4];
            #pragma unroll
            for (int mt = 0; mt < 2; mt++)
                ldsm4(af[mt], sA + arowoff + mt * (16 * ROWB) + ks * 32);
            #pragma unroll
            for (int bt = 0; bt < 4; bt++)
                ldsm4(br[bt], sB + browoff + bt * (16 * ROWB) + ks * 32);
            #pragma unroll
            for (int mt = 0; mt < 2; mt++)
                #pragma unroll
                for (int bt = 0; bt < 4; bt++) {
                    mma16816(acc[mt][2 * bt],     af[mt], br[bt][0], br[bt][2]);
                    mma16816(acc[mt][2 * bt + 1], af[mt], br[bt][1], br[bt][3]);
                }
        }
    }

    // epilogue: acc[mt][nt][4] -> C
    int rbase = bm + wm + (l >> 2);
    int cbase = bn + wn + 2 * (l & 3);
    #pragma unroll
    for (int mt = 0; mt < 2; mt++) {
        #pragma unroll
        for (int nt = 0; nt < 8; nt++) {
            int col = cbase + nt * 8;
            float bx = bias[col], by = bias[col + 1];
            int r0 = rbase + mt * 16;
            int r1 = r0 + 8;
            float2 v0, v1;
            v0.x = acc[mt][nt][0] + bx;
            v0.y = acc[mt][nt][1] + by;
            v1.x = acc[mt][nt][2] + bx;
            v1.y = acc[mt][nt][3] + by;
            if (add_res) {
                float2 q0 = *(const float2*)(res + (size_t)r0 * EMB + col);
                float2 q1 = *(const float2*)(res + (size_t)r1 * EMB + col);
                v0.x += q0.x; v0.y += q0.y;
                v1.x += q1.x; v1.y += q1.y;
            }
            *(float2*)(C + (size_t)r0 * EMB + col) = v0;
            *(float2*)(C + (size_t)r1 * EMB + col) = v1;
        }
    }
}

// ---------------- sliding-window attention -> split bf16 output ------------
__global__ void __launch_bounds__(512) attn_kernel(
    const float* __restrict__ Q,
    const float* __restrict__ K,
    const float* __restrict__ V,
    __nv_bfloat16* __restrict__ O2)
{
    int s = blockIdx.x;
    int b = blockIdx.y;
    int h = threadIdx.x >> 5;
    int lane = threadIdx.x & 31;
    int t = s * BSZ + b;

    const float* qp = Q + (size_t)t * EMB + h * DHD;
    float q0 = qp[lane];
    float q1 = qp[lane + 32];

    float sc[PFW];
    #pragma unroll
    for (int p = 0; p < PFW; p++) {
        int sp = s + p - (PFW - 1);
        if (sp < 0) sp += SLEN;
        const float* kp = K + (size_t)(sp * BSZ + b) * EMB + h * DHD;
        float d = q0 * kp[lane] + q1 * kp[lane + 32];
        #pragma unroll
        for (int o = 16; o > 0; o >>= 1) d += __shfl_xor_sync(0xffffffffu, d, o);
        sc[p] = d * 0.125f;
    }

    float mx = sc[0];
    #pragma unroll
    for (int p = 1; p < PFW; p++) mx = fmaxf(mx, sc[p]);
    float sum = 0.f;
    #pragma unroll
    for (int p = 0; p < PFW; p++) { sc[p] = __expf(sc[p] - mx); sum += sc[p]; }
    float inv = 1.0f / sum;

    float o0 = 0.f, o1 = 0.f;
    #pragma unroll
    for (int p = 0; p < PFW; p++) {
        int sp = s + p - (PFW - 1);
        if (sp < 0) sp += SLEN;
        const float* vp = V + (size_t)(sp * BSZ + b) * EMB + h * DHD;
        float wgt = sc[p] * inv;
        o0 += wgt * vp[lane];
        o1 += wgt * vp[lane + 32];
    }
    __nv_bfloat16 h0 = __float2bfloat16(o0);
    __nv_bfloat16 l0 = __float2bfloat16(o0 - __bfloat162float(h0));
    __nv_bfloat16 h1 = __float2bfloat16(o1);
    __nv_bfloat16 l1 = __float2bfloat16(o1 - __bfloat162float(h1));
    __nv_bfloat16* op = O2 + (size_t)t * KTOT + h * DHD;
    op[lane]            = h0;  op[lane + 32]            = h1;   // seg0 hi
    op[EMB + lane]      = l0;  op[EMB + lane + 32]      = l1;   // seg1 lo
    op[2*EMB + lane]    = h0;  op[2*EMB + lane + 32]    = h1;   // seg2 hi
}

// ---------------- launch ----------------------------------------------------
extern "C" void kernel_launch(void* const* d_in, const int* in_sizes, int n_in,
                              void* d_out, int out_size)
{
    const float* x    = (const float*)d_in[0];
    const float* ln_g = (const float*)d_in[1];
    const float* ln_b = (const float*)d_in[2];
    const float* Wq   = (const float*)d_in[3];
    const float* bq   = (const float*)d_in[4];
    const float* Wk   = (const float*)d_in[5];
    const float* bk   = (const float*)d_in[6];
    const float* Wv   = (const float*)d_in[7];
    const float* bv   = (const float*)d_in[8];
    const float* Wo   = (const float*)d_in[9];
    const float* bo   = (const float*)d_in[10];
    float* out = (float*)d_out;

    __nv_bfloat16 *xn2, *att2, *w2;
    float *q, *k, *v;
    cudaGetSymbolAddress((void**)&xn2,  g_xn2);
    cudaGetSymbolAddress((void**)&att2, g_att2);
    cudaGetSymbolAddress((void**)&w2,   g_w2);
    cudaGetSymbolAddress((void**)&q,    g_q);
    cudaGetSymbolAddress((void**)&k,    g_k);
    cudaGetSymbolAddress((void**)&v,    g_v);

    cudaFuncSetAttribute(gemm_mma, cudaFuncAttributeMaxDynamicSharedMemorySize, GEMM_SMEM);

    wprep_kernel<<<dim3(32, 32, 4), 256>>>(Wq, Wk, Wv, Wo, w2);
    ln_kernel<<<MTOK, 256>>>(x, ln_g, ln_b, xn2);

    dim3 gg(EMB / GBN, MTOK / GBM);   // (4, 32)
    const size_t WSTRIDE = (size_t)EMB * KTOT;
    gemm_mma<<<gg, GTHR, GEMM_SMEM>>>(xn2, w2 + 0*WSTRIDE, bq, x, q, 0);
    gemm_mma<<<gg, GTHR, GEMM_SMEM>>>(xn2, w2 + 1*WSTRIDE, bk, x, k, 0);
    gemm_mma<<<gg, GTHR, GEMM_SMEM>>>(xn2, w2 + 2*WSTRIDE, bv, x, v, 0);

    attn_kernel<<<dim3(SLEN, BSZ), 512>>>(q, k, v, att2);

    gemm_mma<<<gg, GTHR, GEMM_SMEM>>>(att2, w2 + 3*WSTRIDE, bo, x, out, 1);
}

// round 5
// speedup vs baseline: 2.5776x; 1.2385x over previous
#include <cuda_runtime.h>
#include <cuda_fp16.h>
#include <cstdint>

#define SLEN 2048
#define BSZ  2
#define EMB  1024
#define NH   16
#define DHD  64
#define PFW  16
#define MTOK (SLEN*BSZ)
#define KAE  2048            // A split width (hi | lo)
#define GBK  32              // original-K per chunk
#define NCHUNK 32            // 1024 / 32
#define GBM  128
#define GBN  256
#define STAGES 4
#define ROWB 80              // padded smem row bytes (64 data + 16 pad)
#define SROWS 512            // A-hi 128 + A-lo 128 + B 256
#define STGB (SROWS*ROWB)    // 40960
#define GEMM_SMEM (STAGES*STGB)  // 163840
#define GTHR 512
#define NQKV 3072

// ---------------- scratch (static device arrays; no allocation) -------------
__device__ __align__(16) __half g_xn2 [MTOK*KAE];       // LN out (hi|lo)
__device__ __align__(16) __half g_att2[MTOK*KAE];       // attn out (hi|lo)
__device__ __align__(16) __half g_wh  [4*EMB*EMB];      // Wq|Wk|Wv|Wo hi, [N][K]
__device__ float g_qkv[MTOK*NQKV];                      // fused QKV output
__device__ float g_bias[NQKV];

// ---------------- PTX helpers ------------------------------------------------
__device__ __forceinline__ uint32_t s2u(const void* p) {
    uint32_t a;
    asm("{ .reg .u64 t; cvta.to.shared.u64 t, %1; cvt.u32.u64 %0, t; }" : "=r"(a) : "l"(p));
    return a;
}
__device__ __forceinline__ void cp16(uint32_t dst, const void* src) {
    asm volatile("cp.async.cg.shared.global [%0], [%1], 16;" :: "r"(dst), "l"(src));
}
#define CP_COMMIT() asm volatile("cp.async.commit_group;" ::: "memory")

__device__ __forceinline__ void ldsm4(uint32_t* r, uint32_t addr) {
    asm volatile("ldmatrix.sync.aligned.m8n8.x4.shared.b16 {%0,%1,%2,%3}, [%4];"
        : "=r"(r[0]), "=r"(r[1]), "=r"(r[2]), "=r"(r[3]) : "r"(addr));
}
__device__ __forceinline__ void mma16816(float* d, const uint32_t* a,
                                         uint32_t b0, uint32_t b1) {
    asm volatile("mma.sync.aligned.m16n8k16.row.col.f32.f16.f16.f32 "
        "{%0,%1,%2,%3}, {%4,%5,%6,%7}, {%8,%9}, {%0,%1,%2,%3};"
        : "+f"(d[0]), "+f"(d[1]), "+f"(d[2]), "+f"(d[3])
        : "r"(a[0]), "r"(a[1]), "r"(a[2]), "r"(a[3]), "r"(b0), "r"(b1));
}

// ---------------- weight prep: W[K,N] fp32 -> Wh[N,K] fp16 ------------------
__global__ void __launch_bounds__(256) wprep_kernel(
    const float* __restrict__ W0, const float* __restrict__ W1,
    const float* __restrict__ W2, const float* __restrict__ W3,
    __half* __restrict__ Bh)
{
    const float* W = (blockIdx.z == 0) ? W0 : (blockIdx.z == 1) ? W1
                   : (blockIdx.z == 2) ? W2 : W3;
    __half* B = Bh + (size_t)blockIdx.z * EMB * EMB;
    __shared__ float tile[32][33];
    int n0 = blockIdx.x * 32;
    int k0 = blockIdx.y * 32;
    int tx = threadIdx.x & 31;
    int ty = threadIdx.x >> 5;
    #pragma unroll
    for (int r = ty; r < 32; r += 8)
        tile[r][tx] = W[(size_t)(k0 + r) * EMB + n0 + tx];   // tile[k][n]
    __syncthreads();
    #pragma unroll
    for (int r = ty; r < 32; r += 8)
        B[(size_t)(n0 + r) * EMB + (k0 + tx)] = __float2half(tile[tx][r]);
}

__global__ void bias_cat_kernel(const float* __restrict__ bq,
                                const float* __restrict__ bk,
                                const float* __restrict__ bv,
                                float* __restrict__ bqkv)
{
    int i = blockIdx.x * 256 + threadIdx.x;
    if (i < NQKV)
        bqkv[i] = (i < EMB) ? bq[i] : (i < 2*EMB) ? bk[i - EMB] : bv[i - 2*EMB];
}

// ---------------- LayerNorm -> split fp16 A' = (hi | lo) -------------------
__global__ void __launch_bounds__(256) ln_kernel(
    const float* __restrict__ x,
    const float* __restrict__ gamma,
    const float* __restrict__ beta,
    __half* __restrict__ xn2)
{
    int row = blockIdx.x;
    int tid = threadIdx.x;
    const float4 xv = ((const float4*)(x + (size_t)row * EMB))[tid];
    float s  = xv.x + xv.y + xv.z + xv.w;
    float s2 = xv.x*xv.x + xv.y*xv.y + xv.z*xv.z + xv.w*xv.w;
    #pragma unroll
    for (int o = 16; o > 0; o >>= 1) {
        s  += __shfl_xor_sync(0xffffffffu, s,  o);
        s2 += __shfl_xor_sync(0xffffffffu, s2, o);
    }
    __shared__ float rs[8], rs2[8];
    __shared__ float mean_s, rstd_s;
    int w = tid >> 5, l = tid & 31;
    if (l == 0) { rs[w] = s; rs2[w] = s2; }
    __syncthreads();
    if (tid == 0) {
        float ts = 0.f, ts2 = 0.f;
        #pragma unroll
        for (int i = 0; i < 8; i++) { ts += rs[i]; ts2 += rs2[i]; }
        float mean = ts * (1.0f / EMB);
        float var  = ts2 * (1.0f / EMB) - mean * mean;
        mean_s = mean;
        rstd_s = rsqrtf(var + 1e-5f);
    }
    __syncthreads();
    float mean = mean_s, r = rstd_s;
    float4 gv = ((const float4*)gamma)[tid];
    float4 bv = ((const float4*)beta)[tid];
    float o[4];
    o[0] = (xv.x - mean) * r * gv.x + bv.x;
    o[1] = (xv.y - mean) * r * gv.y + bv.y;
    o[2] = (xv.z - mean) * r * gv.z + bv.z;
    o[3] = (xv.w - mean) * r * gv.w + bv.w;
    __half hi[4], lo[4];
    #pragma unroll
    for (int i = 0; i < 4; i++) {
        hi[i] = __float2half(o[i]);
        lo[i] = __float2half(o[i] - __half2float(hi[i]));
    }
    __half* base = xn2 + (size_t)row * KAE + tid * 4;
    *(uint2*)(base)       = *(uint2*)hi;   // hi segment
    *(uint2*)(base + EMB) = *(uint2*)lo;   // lo segment
}

// ---------------- HMMA fp16 GEMM: C = (Ahi+Alo) @ Bh^T + bias (+res) -------
// A2: [M, 2048] fp16 (hi|lo).  Bh: [N, 1024] fp16.
// CTA tile 128x(256 of N), 16 warps, warp tile 32x64, 4-stage cp.async.
__global__ void __launch_bounds__(GTHR, 1) gemm_mma(
    const __half* __restrict__ A2,
    const __half* __restrict__ Bh,
    const float* __restrict__ bias,
    const float* __restrict__ res,
    float* __restrict__ C,
    int ldc, int add_res)
{
    extern __shared__ char smem[];
    uint32_t sb = s2u(smem);
    int tid = threadIdx.x;
    int w = tid >> 5, l = tid & 31;
    int bm = blockIdx.y * GBM;
    int bn = blockIdx.x * GBN;
    int wm = (w & 3) * 32;
    int wn = (w >> 2) * 64;

    // per-thread load assignment: one smem row each (hoisted addressing)
    const __half* src;
    if (tid < 128)       src = A2 + (size_t)(bm + tid) * KAE;              // A hi
    else if (tid < 256)  src = A2 + (size_t)(bm + tid - 128) * KAE + EMB;  // A lo
    else                 src = Bh + (size_t)(bn + tid - 256) * EMB;        // B
    uint32_t rowoff = (uint32_t)tid * ROWB;

    float acc[2][8][4];
    #pragma unroll
    for (int i = 0; i < 2; i++)
        #pragma unroll
        for (int j = 0; j < 8; j++)
            #pragma unroll
            for (int t = 0; t < 4; t++) acc[i][j][t] = 0.f;

    // prologue: fill STAGES-1 stages
    #pragma unroll
    for (int c = 0; c < STAGES - 1; c++) {
        uint32_t d = sb + c * STGB + rowoff;
        #pragma unroll
        for (int ch = 0; ch < 4; ch++) cp16(d + ch * 16, src + ch * 8);
        src += GBK;
        CP_COMMIT();
    }

    uint32_t arow = (uint32_t)(wm + (l & 15)) * ROWB + ((l >> 4) << 4);
    uint32_t brow = (uint32_t)(wn + (l & 15)) * ROWB + ((l >> 4) << 4);

    for (int c = 0; c < NCHUNK; c++) {
        asm volatile("cp.async.wait_group %0;" :: "n"(STAGES - 2) : "memory");
        __syncthreads();
        uint32_t stg = sb + (uint32_t)(c & (STAGES - 1)) * STGB;

        // issue next-stage loads first (overlap with MMA)
        if (c + STAGES - 1 < NCHUNK) {
            uint32_t d = sb + (uint32_t)((c + STAGES - 1) & (STAGES - 1)) * STGB + rowoff;
            #pragma unroll
            for (int ch = 0; ch < 4; ch++) cp16(d + ch * 16, src + ch * 8);
            src += GBK;
        }
        CP_COMMIT();

        uint32_t sAh = stg + arow;
        uint32_t sAl = stg + 128 * ROWB + arow;
        uint32_t sBB = stg + 256 * ROWB + brow;

        #pragma unroll
        for (int ks = 0; ks < 2; ks++) {
            uint32_t ah[2][4], al[2][4], br[4][4];
            #pragma unroll
            for (int mt = 0; mt < 2; mt++) {
                ldsm4(ah[mt], sAh + mt * (16 * ROWB) + ks * 32);
                ldsm4(al[mt], sAl + mt * (16 * ROWB) + ks * 32);
            }
            #pragma unroll
            for (int bt = 0; bt < 4; bt++)
                ldsm4(br[bt], sBB + bt * (16 * ROWB) + ks * 32);
            #pragma unroll
            for (int mt = 0; mt < 2; mt++)
                #pragma unroll
                for (int bt = 0; bt < 4; bt++) {
                    mma16816(acc[mt][2 * bt],     ah[mt], br[bt][0], br[bt][2]);
                    mma16816(acc[mt][2 * bt + 1], ah[mt], br[bt][1], br[bt][3]);
                    mma16816(acc[mt][2 * bt],     al[mt], br[bt][0], br[bt][2]);
                    mma16816(acc[mt][2 * bt + 1], al[mt], br[bt][1], br[bt][3]);
                }
        }
    }

    // epilogue
    int rbase = bm + wm + (l >> 2);
    int cbase = bn + wn + 2 * (l & 3);
    #pragma unroll
    for (int mt = 0; mt < 2; mt++) {
        #pragma unroll
        for (int nt = 0; nt < 8; nt++) {
            int col = cbase + nt * 8;
            float bx = bias[col], by = bias[col + 1];
            int r0 = rbase + mt * 16;
            int r1 = r0 + 8;
            float2 v0, v1;
            v0.x = acc[mt][nt][0] + bx;
            v0.y = acc[mt][nt][1] + by;
            v1.x = acc[mt][nt][2] + bx;
            v1.y = acc[mt][nt][3] + by;
            if (add_res) {
                float2 q0 = *(const float2*)(res + (size_t)r0 * EMB + col);
                float2 q1 = *(const float2*)(res + (size_t)r1 * EMB + col);
                v0.x += q0.x; v0.y += q0.y;
                v1.x += q1.x; v1.y += q1.y;
            }
            *(float2*)(C + (size_t)r0 * ldc + col) = v0;
            *(float2*)(C + (size_t)r1 * ldc + col) = v1;
        }
    }
}

// ---------------- sliding-window attention -> split fp16 output ------------
__global__ void __launch_bounds__(512) attn_kernel(
    const float* __restrict__ QKV,
    __half* __restrict__ O2)
{
    int s = blockIdx.x;
    int b = blockIdx.y;
    int h = threadIdx.x >> 5;
    int lane = threadIdx.x & 31;
    int t = s * BSZ + b;

    const float* qp = QKV + (size_t)t * NQKV + h * DHD;
    float q0 = qp[lane];
    float q1 = qp[lane + 32];

    float sc[PFW];
    #pragma unroll
    for (int p = 0; p < PFW; p++) {
        int sp = s + p - (PFW - 1);
        if (sp < 0) sp += SLEN;
        const float* kp = QKV + (size_t)(sp * BSZ + b) * NQKV + EMB + h * DHD;
        float d = q0 * kp[lane] + q1 * kp[lane + 32];
        #pragma unroll
        for (int o = 16; o > 0; o >>= 1) d += __shfl_xor_sync(0xffffffffu, d, o);
        sc[p] = d * 0.125f;
    }

    float mx = sc[0];
    #pragma unroll
    for (int p = 1; p < PFW; p++) mx = fmaxf(mx, sc[p]);
    float sum = 0.f;
    #pragma unroll
    for (int p = 0; p < PFW; p++) { sc[p] = __expf(sc[p] - mx); sum += sc[p]; }
    float inv = 1.0f / sum;

    float o0 = 0.f, o1 = 0.f;
    #pragma unroll
    for (int p = 0; p < PFW; p++) {
        int sp = s + p - (PFW - 1);
        if (sp < 0) sp += SLEN;
        const float* vp = QKV + (size_t)(sp * BSZ + b) * NQKV + 2 * EMB + h * DHD;
        float wgt = sc[p] * inv;
        o0 += wgt * vp[lane];
        o1 += wgt * vp[lane + 32];
    }
    __half h0 = __float2half(o0);
    __half l0 = __float2half(o0 - __half2float(h0));
    __half h1 = __float2half(o1);
    __half l1 = __float2half(o1 - __half2float(h1));
    __half* op = O2 + (size_t)t * KAE + h * DHD;
    op[lane]          = h0;  op[lane + 32]          = h1;   // hi
    op[EMB + lane]    = l0;  op[EMB + lane + 32]    = l1;   // lo
}

// ---------------- launch ----------------------------------------------------
extern "C" void kernel_launch(void* const* d_in, const int* in_sizes, int n_in,
                              void* d_out, int out_size)
{
    const float* x    = (const float*)d_in[0];
    const float* ln_g = (const float*)d_in[1];
    const float* ln_b = (const float*)d_in[2];
    const float* Wq   = (const float*)d_in[3];
    const float* bq   = (const float*)d_in[4];
    const float* Wk   = (const float*)d_in[5];
    const float* bk   = (const float*)d_in[6];
    const float* Wv   = (const float*)d_in[7];
    const float* bv   = (const float*)d_in[8];
    const float* Wo   = (const float*)d_in[9];
    const float* bo   = (const float*)d_in[10];
    float* out = (float*)d_out;

    __half *xn2, *att2, *wh;
    float *qkv, *bias;
    cudaGetSymbolAddress((void**)&xn2,  g_xn2);
    cudaGetSymbolAddress((void**)&att2, g_att2);
    cudaGetSymbolAddress((void**)&wh,   g_wh);
    cudaGetSymbolAddress((void**)&qkv,  g_qkv);
    cudaGetSymbolAddress((void**)&bias, g_bias);

    cudaFuncSetAttribute(gemm_mma, cudaFuncAttributeMaxDynamicSharedMemorySize, GEMM_SMEM);

    wprep_kernel<<<dim3(32, 32, 4), 256>>>(Wq, Wk, Wv, Wo, wh);
    bias_cat_kernel<<<12, 256>>>(bq, bk, bv, bias);
    ln_kernel<<<MTOK, 256>>>(x, ln_g, ln_b, xn2);

    // fused QKV: C[4096, 3072]
    gemm_mma<<<dim3(NQKV / GBN, MTOK / GBM), GTHR, GEMM_SMEM>>>(
        xn2, wh, bias, nullptr, qkv, NQKV, 0);

    attn_kernel<<<dim3(SLEN, BSZ), 512>>>(qkv, att2);

    // output projection + residual
    gemm_mma<<<dim3(EMB / GBN, MTOK / GBM), GTHR, GEMM_SMEM>>>(
        att2, wh + (size_t)3 * EMB * EMB, bo, x, out, EMB, 1);
}

// round 6
// speedup vs baseline: 4.8365x; 1.8763x over previous
#include <cuda_runtime.h>
#include <cuda_fp16.h>
#include <cstdint>

#define SLEN 2048
#define BSZ  2
#define EMB  1024
#define NH   16
#define DHD  64
#define PFW  16
#define MTOK (SLEN*BSZ)
#define GBK  32              // K per chunk
#define NCHUNK (EMB/GBK)     // 32
#define GBM  128
#define GBN  256
#define STAGES 4
#define ROWB 80              // padded smem row bytes (64 data + 16 pad)
#define SROWS 384            // A 128 rows + B 256 rows
#define STGB (SROWS*ROWB)    // 30720
#define GEMM_SMEM (STAGES*STGB)  // 122880
#define GTHR 512
#define NQKV 3072

// ---------------- scratch (static device arrays; no allocation) -------------
__device__ __align__(16) __half g_xn [MTOK*EMB];        // LN out fp16
__device__ __align__(16) __half g_att[MTOK*EMB];        // attn out fp16
__device__ __align__(16) __half g_wh [4*EMB*EMB];       // Wq|Wk|Wv|Wo fp16, [N][K]
__device__ float g_qkv[MTOK*NQKV];                      // fused QKV output
__device__ float g_bias[NQKV];

// ---------------- PTX helpers ------------------------------------------------
__device__ __forceinline__ uint32_t s2u(const void* p) {
    uint32_t a;
    asm("{ .reg .u64 t; cvta.to.shared.u64 t, %1; cvt.u32.u64 %0, t; }" : "=r"(a) : "l"(p));
    return a;
}
__device__ __forceinline__ void cp16(uint32_t dst, const void* src) {
    asm volatile("cp.async.cg.shared.global [%0], [%1], 16;" :: "r"(dst), "l"(src));
}
#define CP_COMMIT() asm volatile("cp.async.commit_group;" ::: "memory")

__device__ __forceinline__ void ldsm4(uint32_t* r, uint32_t addr) {
    asm volatile("ldmatrix.sync.aligned.m8n8.x4.shared.b16 {%0,%1,%2,%3}, [%4];"
        : "=r"(r[0]), "=r"(r[1]), "=r"(r[2]), "=r"(r[3]) : "r"(addr));
}
__device__ __forceinline__ void mma16816(float* d, const uint32_t* a,
                                         uint32_t b0, uint32_t b1) {
    asm volatile("mma.sync.aligned.m16n8k16.row.col.f32.f16.f16.f32 "
        "{%0,%1,%2,%3}, {%4,%5,%6,%7}, {%8,%9}, {%0,%1,%2,%3};"
        : "+f"(d[0]), "+f"(d[1]), "+f"(d[2]), "+f"(d[3])
        : "r"(a[0]), "r"(a[1]), "r"(a[2]), "r"(a[3]), "r"(b0), "r"(b1));
}

// ---------------- weight prep: W[K,N] fp32 -> Wh[N,K] fp16 ------------------
__global__ void __launch_bounds__(256) wprep_kernel(
    const float* __restrict__ W0, const float* __restrict__ W1,
    const float* __restrict__ W2, const float* __restrict__ W3,
    __half* __restrict__ Bh)
{
    const float* W = (blockIdx.z == 0) ? W0 : (blockIdx.z == 1) ? W1
                   : (blockIdx.z == 2) ? W2 : W3;
    __half* B = Bh + (size_t)blockIdx.z * EMB * EMB;
    __shared__ float tile[32][33];
    int n0 = blockIdx.x * 32;
    int k0 = blockIdx.y * 32;
    int tx = threadIdx.x & 31;
    int ty = threadIdx.x >> 5;
    #pragma unroll
    for (int r = ty; r < 32; r += 8)
        tile[r][tx] = W[(size_t)(k0 + r) * EMB + n0 + tx];   // tile[k][n]
    __syncthreads();
    #pragma unroll
    for (int r = ty; r < 32; r += 8)
        B[(size_t)(n0 + r) * EMB + (k0 + tx)] = __float2half(tile[tx][r]);
}

__global__ void bias_cat_kernel(const float* __restrict__ bq,
                                const float* __restrict__ bk,
                                const float* __restrict__ bv,
                                float* __restrict__ bqkv)
{
    int i = blockIdx.x * 256 + threadIdx.x;
    if (i < NQKV)
        bqkv[i] = (i < EMB) ? bq[i] : (i < 2*EMB) ? bk[i - EMB] : bv[i - 2*EMB];
}

// ---------------- LayerNorm -> fp16 ----------------------------------------
__global__ void __launch_bounds__(256) ln_kernel(
    const float* __restrict__ x,
    const float* __restrict__ gamma,
    const float* __restrict__ beta,
    __half* __restrict__ xn)
{
    int row = blockIdx.x;
    int tid = threadIdx.x;
    const float4 xv = ((const float4*)(x + (size_t)row * EMB))[tid];
    float s  = xv.x + xv.y + xv.z + xv.w;
    float s2 = xv.x*xv.x + xv.y*xv.y + xv.z*xv.z + xv.w*xv.w;
    #pragma unroll
    for (int o = 16; o > 0; o >>= 1) {
        s  += __shfl_xor_sync(0xffffffffu, s,  o);
        s2 += __shfl_xor_sync(0xffffffffu, s2, o);
    }
    __shared__ float rs[8], rs2[8];
    __shared__ float mean_s, rstd_s;
    int w = tid >> 5, l = tid & 31;
    if (l == 0) { rs[w] = s; rs2[w] = s2; }
    __syncthreads();
    if (tid == 0) {
        float ts = 0.f, ts2 = 0.f;
        #pragma unroll
        for (int i = 0; i < 8; i++) { ts += rs[i]; ts2 += rs2[i]; }
        float mean = ts * (1.0f / EMB);
        float var  = ts2 * (1.0f / EMB) - mean * mean;
        mean_s = mean;
        rstd_s = rsqrtf(var + 1e-5f);
    }
    __syncthreads();
    float mean = mean_s, r = rstd_s;
    float4 gv = ((const float4*)gamma)[tid];
    float4 bv = ((const float4*)beta)[tid];
    __half h[4];
    h[0] = __float2half((xv.x - mean) * r * gv.x + bv.x);
    h[1] = __float2half((xv.y - mean) * r * gv.y + bv.y);
    h[2] = __float2half((xv.z - mean) * r * gv.z + bv.z);
    h[3] = __float2half((xv.w - mean) * r * gv.w + bv.w);
    *(uint2*)(xn + (size_t)row * EMB + tid * 4) = *(uint2*)h;
}

// ---------------- HMMA fp16 GEMM: C = A @ B^T + bias (+res) ----------------
// A: [M, 1024] fp16.  B: [N, 1024] fp16 ([N][K]).
// CTA tile 128x256, 16 warps, warp tile 32x64, 4-stage cp.async.
__global__ void __launch_bounds__(GTHR, 1) gemm_mma(
    const __half* __restrict__ A,
    const __half* __restrict__ B,
    const float* __restrict__ bias,
    const float* __restrict__ res,
    float* __restrict__ C,
    int ldc, int add_res)
{
    extern __shared__ char smem[];
    uint32_t sb = s2u(smem);
    int tid = threadIdx.x;
    int w = tid >> 5, l = tid & 31;
    int bm = blockIdx.y * GBM;
    int bn = blockIdx.x * GBN;
    int wm = (w & 3) * 32;
    int wn = (w >> 2) * 64;

    // hoisted load addressing: each thread owns 3 (row, 16B-chunk) slots
    int r0 = tid >> 2;           // 0..127
    int ch = tid & 3;
    const __half* p0 = A + (size_t)(bm + r0) * EMB + ch * 8;        // A row r0
    const __half* p1 = B + (size_t)(bn + r0) * EMB + ch * 8;        // B row r0
    const __half* p2 = B + (size_t)(bn + r0 + 128) * EMB + ch * 8;  // B row r0+128
    uint32_t d0 = (uint32_t)r0 * ROWB + ch * 16;
    uint32_t d1 = d0 + 128 * ROWB;
    uint32_t d2 = d0 + 256 * ROWB;

    float acc[2][8][4];
    #pragma unroll
    for (int i = 0; i < 2; i++)
        #pragma unroll
        for (int j = 0; j < 8; j++)
            #pragma unroll
            for (int t = 0; t < 4; t++) acc[i][j][t] = 0.f;

    // prologue: fill STAGES-1 stages
    #pragma unroll
    for (int c = 0; c < STAGES - 1; c++) {
        uint32_t stg = sb + c * STGB;
        cp16(stg + d0, p0); p0 += GBK;
        cp16(stg + d1, p1); p1 += GBK;
        cp16(stg + d2, p2); p2 += GBK;
        CP_COMMIT();
    }

    uint32_t arow = (uint32_t)(wm + (l & 15)) * ROWB + ((l >> 4) << 4);
    uint32_t brow = (uint32_t)(128 + wn + (l & 15)) * ROWB + ((l >> 4) << 4);

    for (int c = 0; c < NCHUNK; c++) {
        asm volatile("cp.async.wait_group %0;" :: "n"(STAGES - 2) : "memory");
        __syncthreads();
        uint32_t stg = sb + (uint32_t)(c & (STAGES - 1)) * STGB;

        // issue next-stage loads first (overlap with MMA)
        if (c + STAGES - 1 < NCHUNK) {
            uint32_t ds = sb + (uint32_t)((c + STAGES - 1) & (STAGES - 1)) * STGB;
            cp16(ds + d0, p0); p0 += GBK;
            cp16(ds + d1, p1); p1 += GBK;
            cp16(ds + d2, p2); p2 += GBK;
        }
        CP_COMMIT();

        uint32_t sA = stg + arow;
        uint32_t sB = stg + brow;

        #pragma unroll
        for (int ks = 0; ks < 2; ks++) {
            uint32_t af[2][4], br[4][4];
            #pragma unroll
            for (int mt = 0; mt < 2; mt++)
                ldsm4(af[mt], sA + mt * (16 * ROWB) + ks * 32);
            #pragma unroll
            for (int bt = 0; bt < 4; bt++)
                ldsm4(br[bt], sB + bt * (16 * ROWB) + ks * 32);
            #pragma unroll
            for (int mt = 0; mt < 2; mt++)
                #pragma unroll
                for (int bt = 0; bt < 4; bt++) {
                    mma16816(acc[mt][2 * bt],     af[mt], br[bt][0], br[bt][2]);
                    mma16816(acc[mt][2 * bt + 1], af[mt], br[bt][1], br[bt][3]);
                }
        }
    }

    // epilogue
    int rbase = bm + wm + (l >> 2);
    int cbase = bn + wn + 2 * (l & 3);
    #pragma unroll
    for (int mt = 0; mt < 2; mt++) {
        #pragma unroll
        for (int nt = 0; nt < 8; nt++) {
            int col = cbase + nt * 8;
            float bx = bias[col], by = bias[col + 1];
            int rr0 = rbase + mt * 16;
            int rr1 = rr0 + 8;
            float2 v0, v1;
            v0.x = acc[mt][nt][0] + bx;
            v0.y = acc[mt][nt][1] + by;
            v1.x = acc[mt][nt][2] + bx;
            v1.y = acc[mt][nt][3] + by;
            if (add_res) {
                float2 q0 = *(const float2*)(res + (size_t)rr0 * EMB + col);
                float2 q1 = *(const float2*)(res + (size_t)rr1 * EMB + col);
                v0.x += q0.x; v0.y += q0.y;
                v1.x += q1.x; v1.y += q1.y;
            }
            *(float2*)(C + (size_t)rr0 * ldc + col) = v0;
            *(float2*)(C + (size_t)rr1 * ldc + col) = v1;
        }
    }
}

// ---------------- sliding-window attention -> fp16 output ------------------
__global__ void __launch_bounds__(512) attn_kernel(
    const float* __restrict__ QKV,
    __half* __restrict__ O)
{
    int s = blockIdx.x;
    int b = blockIdx.y;
    int h = threadIdx.x >> 5;
    int lane = threadIdx.x & 31;
    int t = s * BSZ + b;

    const float* qp = QKV + (size_t)t * NQKV + h * DHD;
    float q0 = qp[lane];
    float q1 = qp[lane + 32];

    float sc[PFW];
    #pragma unroll
    for (int p = 0; p < PFW; p++) {
        int sp = s + p - (PFW - 1);
        if (sp < 0) sp += SLEN;
        const float* kp = QKV + (size_t)(sp * BSZ + b) * NQKV + EMB + h * DHD;
        float d = q0 * kp[lane] + q1 * kp[lane + 32];
        #pragma unroll
        for (int o = 16; o > 0; o >>= 1) d += __shfl_xor_sync(0xffffffffu, d, o);
        sc[p] = d * 0.125f;
    }

    float mx = sc[0];
    #pragma unroll
    for (int p = 1; p < PFW; p++) mx = fmaxf(mx, sc[p]);
    float sum = 0.f;
    #pragma unroll
    for (int p = 0; p < PFW; p++) { sc[p] = __expf(sc[p] - mx); sum += sc[p]; }
    float inv = 1.0f / sum;

    float o0 = 0.f, o1 = 0.f;
    #pragma unroll
    for (int p = 0; p < PFW; p++) {
        int sp = s + p - (PFW - 1);
        if (sp < 0) sp += SLEN;
        const float* vp = QKV + (size_t)(sp * BSZ + b) * NQKV + 2 * EMB + h * DHD;
        float wgt = sc[p] * inv;
        o0 += wgt * vp[lane];
        o1 += wgt * vp[lane + 32];
    }
    __half* op = O + (size_t)t * EMB + h * DHD;
    op[lane]      = __float2half(o0);
    op[lane + 32] = __float2half(o1);
}

// ---------------- launch ----------------------------------------------------
extern "C" void kernel_launch(void* const* d_in, const int* in_sizes, int n_in,
                              void* d_out, int out_size)
{
    const float* x    = (const float*)d_in[0];
    const float* ln_g = (const float*)d_in[1];
    const float* ln_b = (const float*)d_in[2];
    const float* Wq   = (const float*)d_in[3];
    const float* bq   = (const float*)d_in[4];
    const float* Wk   = (const float*)d_in[5];
    const float* bk   = (const float*)d_in[6];
    const float* Wv   = (const float*)d_in[7];
    const float* bv   = (const float*)d_in[8];
    const float* Wo   = (const float*)d_in[9];
    const float* bo   = (const float*)d_in[10];
    float* out = (float*)d_out;

    __half *xn, *att, *wh;
    float *qkv, *bias;
    cudaGetSymbolAddress((void**)&xn,   g_xn);
    cudaGetSymbolAddress((void**)&att,  g_att);
    cudaGetSymbolAddress((void**)&wh,   g_wh);
    cudaGetSymbolAddress((void**)&qkv,  g_qkv);
    cudaGetSymbolAddress((void**)&bias, g_bias);

    cudaFuncSetAttribute(gemm_mma, cudaFuncAttributeMaxDynamicSharedMemorySize, GEMM_SMEM);

    wprep_kernel<<<dim3(32, 32, 4), 256>>>(Wq, Wk, Wv, Wo, wh);
    bias_cat_kernel<<<12, 256>>>(bq, bk, bv, bias);
    ln_kernel<<<MTOK, 256>>>(x, ln_g, ln_b, xn);

    // fused QKV: C[4096, 3072]
    gemm_mma<<<dim3(NQKV / GBN, MTOK / GBM), GTHR, GEMM_SMEM>>>(
        xn, wh, bias, nullptr, qkv, NQKV, 0);

    attn_kernel<<<dim3(SLEN, BSZ), 512>>>(qkv, att);

    // output projection + residual
    gemm_mma<<<dim3(EMB / GBN, MTOK / GBM), GTHR, GEMM_SMEM>>>(
        att, wh + (size_t)3 * EMB * EMB, bo, x, out, EMB, 1);
}